// round 6
// baseline (speedup 1.0000x reference)
#include <cuda_runtime.h>
#include <cuda_bf16.h>
#include <cuda_fp16.h>
#include <math.h>

// Problem constants (match reference)
#define NN   50000
#define EE   800000
#define GG   512
#define INF  128
#define HIDF 128
#define NH   8
#define HD   16
#define OUTC 128

#define SCALE_S 4.0f
#define COS_M 0.8775825618903728f
#define SIN_M 0.4794255386042030f

// ---------------- scratch (device globals; no cudaMalloc allowed) ------------
__device__ __half2 g_feat1h[NN * 64];   // layer-1 features, fp16 (gather table)
__device__ __half2 g_feat2h[NN * 64];   // layer-2 features, fp16 (gather table)
__device__ float g_el1[NN * NH];
__device__ float g_er1[NN * NH];
__device__ float g_h1[NN * HIDF];       // layer-1 output (fp32: residual + gemm2 input)
__device__ float g_el2[NN];
__device__ float g_er2[NN];

__device__ int g_deg[NN];
__device__ int g_cursor[NN];
__device__ int g_rowptr[NN + 1];
__device__ int g_esrc[EE];              // CSR payload: source node id directly

__device__ float g_gsum[GG * HIDF];
__device__ int   g_gcnt[GG];

// ---------------- init: zero accumulators -----------------------------------
__global__ void k_init() {
    int i = blockIdx.x * blockDim.x + threadIdx.x;
    if (i < NN) { g_deg[i] = 0; g_cursor[i] = 0; }
    if (i < GG * HIDF) g_gsum[i] = 0.0f;
    if (i < GG) g_gcnt[i] = 0;
}

// ---------------- TF32 tensor-core GEMM -------------------------------------
// C[M,128] = A[M,128] @ B[128,128], block tile 128x128, 8 warps x 16 rows,
// BK=32, mma.sync.m16n8k8.tf32. Output written as fp16 gather table.
// Fused attn-logit epilogue: MODE 1: 8 heads x 16; MODE 2: 1 head x 128.

__device__ __forceinline__ unsigned f2tf32(float f) {
    unsigned u;
    asm("cvt.rna.tf32.f32 %0, %1;" : "=r"(u) : "f"(f));
    return u;
}

__device__ __forceinline__ void mma_tf32(float* c, unsigned a0, unsigned a1,
                                         unsigned a2, unsigned a3,
                                         unsigned b0, unsigned b1) {
    asm volatile(
        "mma.sync.aligned.m16n8k8.row.col.f32.tf32.tf32.f32 "
        "{%0,%1,%2,%3}, {%4,%5,%6,%7}, {%8,%9}, {%0,%1,%2,%3};"
        : "+f"(c[0]), "+f"(c[1]), "+f"(c[2]), "+f"(c[3])
        : "r"(a0), "r"(a1), "r"(a2), "r"(a3), "r"(b0), "r"(b1));
}

#define AS_STRIDE 36
#define BS_STRIDE 136

template <int MODE>
__global__ void __launch_bounds__(256, 2)
k_gemm(const float* __restrict__ A, const float* __restrict__ B,
       __half2* __restrict__ Ch, int M,
       const float* __restrict__ al, const float* __restrict__ ar,
       float* __restrict__ elo, float* __restrict__ ero) {
    __shared__ __align__(16) unsigned As[128 * AS_STRIDE];
    __shared__ __align__(16) unsigned Bs[32 * BS_STRIDE];

    int tid = threadIdx.x;
    int w = tid >> 5;           // warp 0..7
    int lane = tid & 31;
    int q = lane >> 2;          // 0..7
    int s = lane & 3;           // 0..3
    int rowBase = blockIdx.x * 128;
    int warpRow = w * 16;

    float acc[16][4];
#pragma unroll
    for (int nt = 0; nt < 16; nt++)
#pragma unroll
        for (int j = 0; j < 4; j++) acc[nt][j] = 0.0f;

    for (int k0 = 0; k0 < 128; k0 += 32) {
#pragma unroll
        for (int it = 0; it < 4; it++) {
            int idx = tid + it * 256;
            int r = idx >> 3;
            int c4 = (idx & 7) * 4;
            int gr = rowBase + r;
            float4 v = make_float4(0.f, 0.f, 0.f, 0.f);
            if (gr < M) v = *(const float4*)&A[gr * 128 + k0 + c4];
            unsigned* p = &As[r * AS_STRIDE + c4];
            p[0] = f2tf32(v.x); p[1] = f2tf32(v.y);
            p[2] = f2tf32(v.z); p[3] = f2tf32(v.w);
        }
#pragma unroll
        for (int it = 0; it < 4; it++) {
            int idx = tid + it * 256;
            int r = idx >> 5;
            int c4 = (idx & 31) * 4;
            float4 v = *(const float4*)&B[(k0 + r) * 128 + c4];
            unsigned* p = &Bs[r * BS_STRIDE + c4];
            p[0] = f2tf32(v.x); p[1] = f2tf32(v.y);
            p[2] = f2tf32(v.z); p[3] = f2tf32(v.w);
        }
        __syncthreads();

#pragma unroll
        for (int kk = 0; kk < 32; kk += 8) {
            unsigned a0 = As[(warpRow + q) * AS_STRIDE + kk + s];
            unsigned a1 = As[(warpRow + q + 8) * AS_STRIDE + kk + s];
            unsigned a2 = As[(warpRow + q) * AS_STRIDE + kk + s + 4];
            unsigned a3 = As[(warpRow + q + 8) * AS_STRIDE + kk + s + 4];
#pragma unroll
            for (int nt = 0; nt < 16; nt++) {
                unsigned b0 = Bs[(kk + s) * BS_STRIDE + nt * 8 + q];
                unsigned b1 = Bs[(kk + s + 4) * BS_STRIDE + nt * 8 + q];
                mma_tf32(acc[nt], a0, a1, a2, a3, b0, b1);
            }
        }
        __syncthreads();
    }

    int rA = rowBase + warpRow + q;
    int rB = rA + 8;

    float2 alv[16], arv[16];
#pragma unroll
    for (int nt = 0; nt < 16; nt++) {
        int col = nt * 8 + 2 * s;
        alv[nt] = *(const float2*)&al[col];
        arv[nt] = *(const float2*)&ar[col];
    }

    // store C as fp16 gather table (half2 index = col/2 = nt*4 + s)
    if (rA < M) {
#pragma unroll
        for (int nt = 0; nt < 16; nt++)
            Ch[rA * 64 + nt * 4 + s] = __floats2half2_rn(acc[nt][0], acc[nt][1]);
    }
    if (rB < M) {
#pragma unroll
        for (int nt = 0; nt < 16; nt++)
            Ch[rB * 64 + nt * 4 + s] = __floats2half2_rn(acc[nt][2], acc[nt][3]);
    }

    if (MODE == 1) {
#pragma unroll
        for (int h = 0; h < 8; h++) {
            float plA = 0.f, prA = 0.f, plB = 0.f, prB = 0.f;
#pragma unroll
            for (int k = 2 * h; k <= 2 * h + 1; k++) {
                plA += acc[k][0] * alv[k].x + acc[k][1] * alv[k].y;
                prA += acc[k][0] * arv[k].x + acc[k][1] * arv[k].y;
                plB += acc[k][2] * alv[k].x + acc[k][3] * alv[k].y;
                prB += acc[k][2] * arv[k].x + acc[k][3] * arv[k].y;
            }
            plA += __shfl_xor_sync(0xffffffffu, plA, 1);
            plA += __shfl_xor_sync(0xffffffffu, plA, 2);
            prA += __shfl_xor_sync(0xffffffffu, prA, 1);
            prA += __shfl_xor_sync(0xffffffffu, prA, 2);
            plB += __shfl_xor_sync(0xffffffffu, plB, 1);
            plB += __shfl_xor_sync(0xffffffffu, plB, 2);
            prB += __shfl_xor_sync(0xffffffffu, prB, 1);
            prB += __shfl_xor_sync(0xffffffffu, prB, 2);
            if (s == 0) {
                if (rA < M) { elo[rA * 8 + h] = plA; ero[rA * 8 + h] = prA; }
                if (rB < M) { elo[rB * 8 + h] = plB; ero[rB * 8 + h] = prB; }
            }
        }
    } else {
        float plA = 0.f, prA = 0.f, plB = 0.f, prB = 0.f;
#pragma unroll
        for (int nt = 0; nt < 16; nt++) {
            plA += acc[nt][0] * alv[nt].x + acc[nt][1] * alv[nt].y;
            prA += acc[nt][0] * arv[nt].x + acc[nt][1] * arv[nt].y;
            plB += acc[nt][2] * alv[nt].x + acc[nt][3] * alv[nt].y;
            prB += acc[nt][2] * arv[nt].x + acc[nt][3] * arv[nt].y;
        }
        plA += __shfl_xor_sync(0xffffffffu, plA, 1);
        plA += __shfl_xor_sync(0xffffffffu, plA, 2);
        prA += __shfl_xor_sync(0xffffffffu, prA, 1);
        prA += __shfl_xor_sync(0xffffffffu, prA, 2);
        plB += __shfl_xor_sync(0xffffffffu, plB, 1);
        plB += __shfl_xor_sync(0xffffffffu, plB, 2);
        prB += __shfl_xor_sync(0xffffffffu, prB, 1);
        prB += __shfl_xor_sync(0xffffffffu, prB, 2);
        if (s == 0) {
            if (rA < M) { elo[rA] = plA; ero[rA] = prA; }
            if (rB < M) { elo[rB] = plB; ero[rB] = prB; }
        }
    }
}

// ---------------- CSR build --------------------------------------------------
__global__ void k_hist(const int* __restrict__ dst) {
    int i = blockIdx.x * blockDim.x + threadIdx.x;
    if (i < EE) atomicAdd(&g_deg[dst[i]], 1);
}

// single-block fused scan: 1024 threads, ~49 elements each
__global__ void k_scan() {
    __shared__ int s[1024];
    const int per = (NN + 1023) / 1024;
    int t = threadIdx.x;
    int base = t * per;
    int sum = 0;
    for (int i = 0; i < per; i++) {
        int idx = base + i;
        if (idx < NN) sum += g_deg[idx];
    }
    s[t] = sum;
    __syncthreads();
    for (int off = 1; off < 1024; off <<= 1) {
        int u = (t >= off) ? s[t - off] : 0;
        __syncthreads();
        s[t] += u;
        __syncthreads();
    }
    int run = s[t] - sum;   // exclusive prefix
    for (int i = 0; i < per; i++) {
        int idx = base + i;
        if (idx < NN) {
            g_rowptr[idx] = run;
            run += g_deg[idx];
        }
    }
    if (t == 1023) g_rowptr[NN] = EE;
}

__global__ void k_scatter(const int* __restrict__ dst, const int* __restrict__ src) {
    int i = blockIdx.x * blockDim.x + threadIdx.x;
    if (i < EE) {
        int d = dst[i];
        int pos = g_rowptr[d] + atomicAdd(&g_cursor[d], 1);
        g_esrc[pos] = src[i];
    }
}

// ---------------- fp16 gather helper ----------------------------------------
__device__ __forceinline__ void gather_fma(const uint2* __restrict__ fv,
                                           int node, int lane, float w,
                                           float4& acc) {
    uint2 u = __ldg(&fv[node * 32 + lane]);
    __half2 h0 = *(__half2*)&u.x;
    __half2 h1 = *(__half2*)&u.y;
    float2 f01 = __half22float2(h0);
    float2 f23 = __half22float2(h1);
    acc.x = fmaf(w, f01.x, acc.x);
    acc.y = fmaf(w, f01.y, acc.y);
    acc.z = fmaf(w, f23.x, acc.z);
    acc.w = fmaf(w, f23.y, acc.w);
}

// ---------------- GAT layer 1 aggregation (warp per dst node) ---------------
__global__ void k_agg1(const float* __restrict__ b1) {
    int n = (blockIdx.x * blockDim.x + threadIdx.x) >> 5;
    int lane = threadIdx.x & 31;
    if (n >= NN) return;
    int head = lane >> 2;
    float er_h = g_er1[n * 8 + head];
    int beg = g_rowptr[n], end = g_rowptr[n + 1];
    const uint2* fv = (const uint2*)g_feat1h;
    float4 acc = make_float4(0.f, 0.f, 0.f, 0.f);
    float den = 0.0f;
    int i = beg;
    for (; i + 3 < end; i += 4) {
        int s0 = __ldg(&g_esrc[i]);
        int s1 = __ldg(&g_esrc[i + 1]);
        int s2 = __ldg(&g_esrc[i + 2]);
        int s3 = __ldg(&g_esrc[i + 3]);
        float x0 = __ldg(&g_el1[s0 * 8 + head]) + er_h;
        float x1 = __ldg(&g_el1[s1 * 8 + head]) + er_h;
        float x2 = __ldg(&g_el1[s2 * 8 + head]) + er_h;
        float x3 = __ldg(&g_el1[s3 * 8 + head]) + er_h;
        float w0 = __expf(x0 > 0.0f ? x0 : 0.2f * x0);
        float w1 = __expf(x1 > 0.0f ? x1 : 0.2f * x1);
        float w2 = __expf(x2 > 0.0f ? x2 : 0.2f * x2);
        float w3 = __expf(x3 > 0.0f ? x3 : 0.2f * x3);
        gather_fma(fv, s0, lane, w0, acc);
        gather_fma(fv, s1, lane, w1, acc);
        gather_fma(fv, s2, lane, w2, acc);
        gather_fma(fv, s3, lane, w3, acc);
        den += (w0 + w1) + (w2 + w3);
    }
    for (; i < end; i++) {
        int s0 = __ldg(&g_esrc[i]);
        float x0 = __ldg(&g_el1[s0 * 8 + head]) + er_h;
        float w0 = __expf(x0 > 0.0f ? x0 : 0.2f * x0);
        gather_fma(fv, s0, lane, w0, acc);
        den += w0;
    }
    float inv = den > 0.0f ? 1.0f / den : 0.0f;
    float4 bv = ((const float4*)b1)[lane];
    float4 v;
    v.x = acc.x * inv + bv.x;
    v.y = acc.y * inv + bv.y;
    v.z = acc.z * inv + bv.z;
    v.w = acc.w * inv + bv.w;
    v.x = v.x > 0.0f ? v.x : expm1f(v.x);
    v.y = v.y > 0.0f ? v.y : expm1f(v.y);
    v.z = v.z > 0.0f ? v.z : expm1f(v.z);
    v.w = v.w > 0.0f ? v.w : expm1f(v.w);
    ((float4*)g_h1)[n * 32 + lane] = v;
}

// ---------------- GAT layer 2 aggregation + residual + graph pooling --------
__global__ void k_agg2(const float* __restrict__ b2, const int* __restrict__ graph_ids) {
    int n = (blockIdx.x * blockDim.x + threadIdx.x) >> 5;
    int lane = threadIdx.x & 31;
    if (n >= NN) return;
    float er_n = g_er2[n];
    int beg = g_rowptr[n], end = g_rowptr[n + 1];
    const uint2* fv = (const uint2*)g_feat2h;
    float4 acc = make_float4(0.f, 0.f, 0.f, 0.f);
    float den = 0.0f;
    int i = beg;
    for (; i + 3 < end; i += 4) {
        int s0 = __ldg(&g_esrc[i]);
        int s1 = __ldg(&g_esrc[i + 1]);
        int s2 = __ldg(&g_esrc[i + 2]);
        int s3 = __ldg(&g_esrc[i + 3]);
        float x0 = __ldg(&g_el2[s0]) + er_n;
        float x1 = __ldg(&g_el2[s1]) + er_n;
        float x2 = __ldg(&g_el2[s2]) + er_n;
        float x3 = __ldg(&g_el2[s3]) + er_n;
        float w0 = __expf(x0 > 0.0f ? x0 : 0.2f * x0);
        float w1 = __expf(x1 > 0.0f ? x1 : 0.2f * x1);
        float w2 = __expf(x2 > 0.0f ? x2 : 0.2f * x2);
        float w3 = __expf(x3 > 0.0f ? x3 : 0.2f * x3);
        gather_fma(fv, s0, lane, w0, acc);
        gather_fma(fv, s1, lane, w1, acc);
        gather_fma(fv, s2, lane, w2, acc);
        gather_fma(fv, s3, lane, w3, acc);
        den += (w0 + w1) + (w2 + w3);
    }
    for (; i < end; i++) {
        int s0 = __ldg(&g_esrc[i]);
        float x0 = __ldg(&g_el2[s0]) + er_n;
        float w0 = __expf(x0 > 0.0f ? x0 : 0.2f * x0);
        gather_fma(fv, s0, lane, w0, acc);
        den += w0;
    }
    float inv = den > 0.0f ? 1.0f / den : 0.0f;
    float4 res = ((const float4*)g_h1)[n * 32 + lane];
    float4 bv = ((const float4*)b2)[lane];
    float4 v;
    v.x = acc.x * inv + res.x + bv.x;
    v.y = acc.y * inv + res.y + bv.y;
    v.z = acc.z * inv + res.z + bv.z;
    v.w = acc.w * inv + res.w + bv.w;
    int g = __ldg(&graph_ids[n]);
    float* gs = &g_gsum[g * 128 + lane * 4];
    atomicAdd(&gs[0], v.x);
    atomicAdd(&gs[1], v.y);
    atomicAdd(&gs[2], v.z);
    atomicAdd(&gs[3], v.w);
    if (lane == 0) atomicAdd(&g_gcnt[g], 1);
}

// ---------------- ArcFace head ----------------------------------------------
__global__ void k_arcface(const float* __restrict__ Wa, const int* __restrict__ labels,
                          float* __restrict__ out) {
    __shared__ float emb[128];
    __shared__ float red[128];
    int g = blockIdx.x;
    int t = threadIdx.x;
    float cnt = (float)g_gcnt[g];
    float ic = 1.0f / fmaxf(cnt, 1.0f);
    float e = g_gsum[g * 128 + t] * ic;
    emb[t] = e;
    red[t] = e * e;
    __syncthreads();
    for (int s = 64; s > 0; s >>= 1) {
        if (t < s) red[t] += red[t + s];
        __syncthreads();
    }
    float invn = rsqrtf(red[0]);
    const float* wrow = Wa + t * 128;
    float dot = 0.0f, w2 = 0.0f;
#pragma unroll 4
    for (int k = 0; k < 128; k += 4) {
        float4 wv = *(const float4*)&wrow[k];
        dot += emb[k] * wv.x + emb[k + 1] * wv.y + emb[k + 2] * wv.z + emb[k + 3] * wv.w;
        w2 += wv.x * wv.x + wv.y * wv.y + wv.z * wv.z + wv.w * wv.w;
    }
    float c = dot * rsqrtf(w2) * invn;
    if (t == __ldg(&labels[g])) {
        float s2 = fmaxf(0.0f, 1.0f - c * c);
        c = c * COS_M - sqrtf(s2) * SIN_M;
    }
    out[g * 128 + t] = SCALE_S * c;
}

// ---------------- launcher ---------------------------------------------------
extern "C" void kernel_launch(void* const* d_in, const int* in_sizes, int n_in,
                              void* d_out, int out_size) {
    const float* x   = (const float*)d_in[0];
    const int* src   = (const int*)d_in[1];
    const int* dst   = (const int*)d_in[2];
    const int* gids  = (const int*)d_in[3];
    const int* labels= (const int*)d_in[4];
    const float* W1  = (const float*)d_in[5];
    const float* al1 = (const float*)d_in[6];
    const float* ar1 = (const float*)d_in[7];
    const float* b1  = (const float*)d_in[8];
    const float* W2  = (const float*)d_in[9];
    const float* al2 = (const float*)d_in[10];
    const float* ar2 = (const float*)d_in[11];
    const float* b2  = (const float*)d_in[12];
    const float* Wa  = (const float*)d_in[13];
    float* out = (float*)d_out;

    __half2 *feat1h, *feat2h;
    float *h1, *el1, *er1, *el2, *er2;
    cudaGetSymbolAddress((void**)&feat1h, g_feat1h);
    cudaGetSymbolAddress((void**)&feat2h, g_feat2h);
    cudaGetSymbolAddress((void**)&h1, g_h1);
    cudaGetSymbolAddress((void**)&el1, g_el1);
    cudaGetSymbolAddress((void**)&er1, g_er1);
    cudaGetSymbolAddress((void**)&el2, g_el2);
    cudaGetSymbolAddress((void**)&er2, g_er2);

    const int TB = 256;
    int nWarpBlocks = (NN * 32 + TB - 1) / TB;
    int nEdgeBlocks = (EE + TB - 1) / TB;

    k_init<<<(GG * HIDF + TB - 1) / TB, TB>>>();          // 1

    // CSR build
    k_hist<<<nEdgeBlocks, TB>>>(dst);                     // 2
    k_scan<<<1, 1024>>>();                                // 3
    k_scatter<<<nEdgeBlocks, TB>>>(dst, src);             // 4

    // layer 1 (tensor-core GEMM, fp16 table + attn-logit epilogue)
    k_gemm<1><<<(NN + 127) / 128, 256>>>(x, W1, feat1h, NN, al1, ar1, el1, er1);  // 5
    k_agg1<<<nWarpBlocks, TB>>>(b1);                      // 6  <- ncu -s 5 lands here

    // layer 2
    k_gemm<2><<<(NN + 127) / 128, 256>>>(h1, W2, feat2h, NN, al2, ar2, el2, er2); // 7
    k_agg2<<<nWarpBlocks, TB>>>(b2, gids);                // 8

    // ArcFace head
    k_arcface<<<GG, 128>>>(Wa, labels, out);              // 9
}